// round 1
// baseline (speedup 1.0000x reference)
#include <cuda_runtime.h>
#include <cuda_bf16.h>
#include <stdint.h>

// Problem constants
#define B_  2
#define M_  2048
#define N_  2048
#define D_  1024
#define NH_ 16
#define DH_ 64

// Scratch (device globals: no allocation allowed)
__device__ float g_Q[(size_t)B_ * M_ * D_];   // 16 MB
__device__ float g_K[(size_t)B_ * N_ * D_];   // 16 MB
__device__ float g_V[(size_t)B_ * N_ * D_];   // 16 MB
__device__ float g_C[(size_t)B_ * M_ * D_];   // 16 MB context
__device__ unsigned char g_mask[B_ * N_];     // expanded key-padding mask (1 = ignore)

// ---------------------------------------------------------------------------
// Mask dtype sniffer + expander. The reference produces a bool array; the
// harness may hand it to us as uint8/bool, int32, or float32. We inspect the
// first 4096 bytes (always safe: 4096 elements * >=1 byte) and classify.
// Deterministic for fixed input. Single block.
// ---------------------------------------------------------------------------
__global__ void mask_expand_kernel(const unsigned char* __restrict__ raw) {
    __shared__ int s_not_int, s_not_float;
    if (threadIdx.x == 0) { s_not_int = 0; s_not_float = 0; }
    __syncthreads();
    const unsigned int* w = (const unsigned int*)raw;
    // Inspect first 1024 words (= first 4096 bytes, safe for every hypothesis)
    for (int i = threadIdx.x; i < 1024; i += blockDim.x) {
        unsigned int x = w[i];
        if (x != 0u && x != 1u)            atomicOr(&s_not_int, 1);
        if (x != 0u && x != 0x3F800000u)   atomicOr(&s_not_float, 1);
    }
    __syncthreads();
    int mode = (!s_not_int) ? 0 : ((!s_not_float) ? 1 : 2); // 0=int32, 1=float32, 2=byte
    if (mode == 2) {
        for (int i = threadIdx.x; i < B_ * N_; i += blockDim.x)
            g_mask[i] = raw[i] ? 1 : 0;
    } else {
        for (int i = threadIdx.x; i < B_ * N_; i += blockDim.x)
            g_mask[i] = w[i] ? 1 : 0;   // works for int32 0/1 and f32 0.0/1.0 bit patterns
    }
}

// ---------------------------------------------------------------------------
// SGEMM: C[M,N] = A[M,K] @ B[K,N], all row-major, dims multiples of 128/8.
// 128x128 block tile, K-step 8, 256 threads, 8x8 per-thread micro-tile.
// ---------------------------------------------------------------------------
__global__ __launch_bounds__(256) void sgemm128(
    const float* __restrict__ A, const float* __restrict__ Bm,
    float* __restrict__ C, int Mdim, int Ndim, int Kdim)
{
    __shared__ float As[8][128];
    __shared__ float Bs[8][128];

    const int tid = threadIdx.x;
    const int rowBase = blockIdx.y * 128;
    const int colBase = blockIdx.x * 128;
    const int tx = tid & 15;        // 0..15 -> col micro-tile
    const int ty = tid >> 4;        // 0..15 -> row micro-tile

    // A-tile loader: 128 rows x 8 cols; each thread: one float4
    const int ar = tid >> 1;            // 0..127
    const int ac = (tid & 1) * 4;       // 0 or 4
    // B-tile loader: 8 rows x 128 cols; each thread: one float4
    const int br = tid >> 5;            // 0..7
    const int bc = (tid & 31) * 4;      // 0..124

    const float* Aptr = A + (size_t)(rowBase + ar) * Kdim + ac;
    const float* Bptr = Bm + (size_t)br * Ndim + colBase + bc;

    float acc[8][8];
#pragma unroll
    for (int i = 0; i < 8; ++i)
#pragma unroll
        for (int j = 0; j < 8; ++j) acc[i][j] = 0.f;

    for (int k0 = 0; k0 < Kdim; k0 += 8) {
        float4 av = *(const float4*)(Aptr + k0);
        float4 bv = *(const float4*)(Bptr + (size_t)k0 * Ndim);
        As[ac + 0][ar] = av.x;
        As[ac + 1][ar] = av.y;
        As[ac + 2][ar] = av.z;
        As[ac + 3][ar] = av.w;
        *(float4*)&Bs[br][bc] = bv;
        __syncthreads();

#pragma unroll
        for (int kk = 0; kk < 8; ++kk) {
            float a[8], b[8];
            *(float4*)(a)     = *(const float4*)&As[kk][ty * 8];
            *(float4*)(a + 4) = *(const float4*)&As[kk][ty * 8 + 4];
            *(float4*)(b)     = *(const float4*)&Bs[kk][tx * 8];
            *(float4*)(b + 4) = *(const float4*)&Bs[kk][tx * 8 + 4];
#pragma unroll
            for (int i = 0; i < 8; ++i)
#pragma unroll
                for (int j = 0; j < 8; ++j)
                    acc[i][j] = fmaf(a[i], b[j], acc[i][j]);
        }
        __syncthreads();
    }

#pragma unroll
    for (int i = 0; i < 8; ++i) {
        float* crow = C + (size_t)(rowBase + ty * 8 + i) * Ndim + colBase + tx * 8;
        *(float4*)(crow)     = make_float4(acc[i][0], acc[i][1], acc[i][2], acc[i][3]);
        *(float4*)(crow + 4) = make_float4(acc[i][4], acc[i][5], acc[i][6], acc[i][7]);
    }
}

// ---------------------------------------------------------------------------
// Flash attention, fp32. One warp per query row; block = 32 warps = 32 rows.
// K/V staged per 64-key tile in shared memory as float2 (dh=64 -> 32 float2).
// Online softmax with warp-shuffle reduction. Masked keys -> p = 0.
// Grid: (M/32, NH, B)
// ---------------------------------------------------------------------------
__global__ __launch_bounds__(1024) void attn_kernel(
    const float* __restrict__ Q, const float* __restrict__ K,
    const float* __restrict__ V, float* __restrict__ Cout)
{
    const int mTile = blockIdx.x;
    const int h     = blockIdx.y;
    const int b     = blockIdx.z;
    const int warp  = threadIdx.x >> 5;
    const int lane  = threadIdx.x & 31;
    const int row   = mTile * 32 + warp;

    __shared__ float2 Ks[64][32];
    __shared__ float2 Vs[64][32];
    __shared__ unsigned char msk[64];

    const float scale = 0.125f;  // 1/sqrt(64)

    const float* qptr = Q + ((size_t)(b * M_ + row)) * D_ + h * DH_;
    float2 q = ((const float2*)qptr)[lane];
    q.x *= scale; q.y *= scale;

    float m = -1e30f, l = 0.f;
    float2 acc = make_float2(0.f, 0.f);

    for (int kt = 0; kt < N_ / 64; ++kt) {
        __syncthreads();   // previous tile fully consumed
        // Cooperative tile load: 64 rows x 32 float2 each for K and V
        for (int i = threadIdx.x; i < 64 * 32; i += 1024) {
            int r = i >> 5, c = i & 31;
            int n = kt * 64 + r;
            const float2* kp = (const float2*)(K + ((size_t)(b * N_ + n)) * D_ + h * DH_);
            const float2* vp = (const float2*)(V + ((size_t)(b * N_ + n)) * D_ + h * DH_);
            Ks[r][c] = kp[c];
            Vs[r][c] = vp[c];
        }
        if (threadIdx.x < 64) msk[threadIdx.x] = g_mask[b * N_ + kt * 64 + threadIdx.x];
        __syncthreads();

#pragma unroll 4
        for (int j = 0; j < 64; ++j) {
            float2 kv = Ks[j][lane];
            float s = q.x * kv.x + q.y * kv.y;
            s += __shfl_xor_sync(0xFFFFFFFFu, s, 16);
            s += __shfl_xor_sync(0xFFFFFFFFu, s, 8);
            s += __shfl_xor_sync(0xFFFFFFFFu, s, 4);
            s += __shfl_xor_sync(0xFFFFFFFFu, s, 2);
            s += __shfl_xor_sync(0xFFFFFFFFu, s, 1);
            const bool bad = (msk[j] != 0);
            if (bad) s = -1e30f;
            float mn   = fmaxf(m, s);
            float corr = __expf(m - mn);
            float p    = bad ? 0.f : __expf(s - mn);
            float2 v   = Vs[j][lane];
            l = l * corr + p;
            acc.x = fmaf(acc.x, corr, p * v.x);
            acc.y = fmaf(acc.y, corr, p * v.y);
            m = mn;
        }
    }

    float inv = 1.f / l;
    float2* outp = (float2*)(Cout + ((size_t)(b * M_ + row)) * D_ + h * DH_);
    outp[lane] = make_float2(acc.x * inv, acc.y * inv);
}

// ---------------------------------------------------------------------------
// Launch
// Inputs (metadata order): query, key_value, key_padding_mask, W_Q, W_K, W_V, W_O
// ---------------------------------------------------------------------------
extern "C" void kernel_launch(void* const* d_in, const int* in_sizes, int n_in,
                              void* d_out, int out_size)
{
    const float* query = (const float*)d_in[0];
    const float* keyv  = (const float*)d_in[1];
    const unsigned char* mask_raw = (const unsigned char*)d_in[2];
    const float* W_Q = (const float*)d_in[3];
    const float* W_K = (const float*)d_in[4];
    const float* W_V = (const float*)d_in[5];
    const float* W_O = (const float*)d_in[6];
    float* out = (float*)d_out;

    float *gQ, *gK, *gV, *gC;
    cudaGetSymbolAddress((void**)&gQ, g_Q);
    cudaGetSymbolAddress((void**)&gK, g_K);
    cudaGetSymbolAddress((void**)&gV, g_V);
    cudaGetSymbolAddress((void**)&gC, g_C);

    // 1) mask decode/expand
    mask_expand_kernel<<<1, 1024>>>(mask_raw);

    // 2) projections: (B*M, D) @ (D, NH*DH)
    dim3 gproj(D_ / 128, (B_ * M_) / 128);
    sgemm128<<<gproj, 256>>>(query, W_Q, gQ, B_ * M_, D_, D_);
    sgemm128<<<gproj, 256>>>(keyv,  W_K, gK, B_ * N_, D_, D_);
    sgemm128<<<gproj, 256>>>(keyv,  W_V, gV, B_ * N_, D_, D_);

    // 3) attention
    dim3 gattn(M_ / 32, NH_, B_);
    attn_kernel<<<gattn, 1024>>>(gQ, gK, gV, gC);

    // 4) output projection: (B*M, NH*DH) @ (NH*DH, D) -> d_out
    dim3 gout(D_ / 128, (B_ * M_) / 128);
    sgemm128<<<gout, 256>>>(gC, W_O, out, B_ * M_, D_, D_);
}

// round 2
// speedup vs baseline: 7.1292x; 7.1292x over previous
#include <cuda_runtime.h>
#include <stdint.h>

#define B_  2
#define M_  2048
#define N_  2048
#define D_  1024
#define NH_ 16
#define DH_ 64

// Scratch (device globals: no allocation allowed)
__device__ float g_Q[(size_t)B_ * M_ * D_];
__device__ float g_K[(size_t)B_ * N_ * D_];
__device__ float g_V[(size_t)B_ * N_ * D_];
__device__ float g_C[(size_t)B_ * M_ * D_];
__device__ unsigned char g_mask[B_ * N_];

// ---------------------------------------------------------------------------
// helpers
// ---------------------------------------------------------------------------
__device__ __forceinline__ unsigned f2tf(float x) {
    unsigned u; asm("cvt.rna.tf32.f32 %0, %1;" : "=r"(u) : "f"(x)); return u;
}
__device__ __forceinline__ float ex2(float x) {
    float y; asm("ex2.approx.f32 %0, %1;" : "=f"(y) : "f"(x)); return y;
}
// C(m16n8) += A(m16k8,row) * B(k8n8,col)   tf32
__device__ __forceinline__ void mma8(float* c, unsigned a0, unsigned a1, unsigned a2, unsigned a3,
                                     unsigned b0, unsigned b1) {
    asm volatile(
        "mma.sync.aligned.m16n8k8.row.col.f32.tf32.tf32.f32 "
        "{%0,%1,%2,%3},{%4,%5,%6,%7},{%8,%9},{%0,%1,%2,%3};\n"
        : "+f"(c[0]), "+f"(c[1]), "+f"(c[2]), "+f"(c[3])
        : "r"(a0), "r"(a1), "r"(a2), "r"(a3), "r"(b0), "r"(b1));
}

// ---------------------------------------------------------------------------
// Mask dtype sniffer + expander (bool may arrive as u8 / i32 / f32)
// ---------------------------------------------------------------------------
__global__ void mask_expand_kernel(const unsigned char* __restrict__ raw) {
    __shared__ int s_not_int, s_not_float;
    if (threadIdx.x == 0) { s_not_int = 0; s_not_float = 0; }
    __syncthreads();
    const unsigned int* w = (const unsigned int*)raw;
    for (int i = threadIdx.x; i < 1024; i += blockDim.x) {
        unsigned int x = w[i];
        if (x != 0u && x != 1u)          atomicOr(&s_not_int, 1);
        if (x != 0u && x != 0x3F800000u) atomicOr(&s_not_float, 1);
    }
    __syncthreads();
    int mode = (!s_not_int) ? 0 : ((!s_not_float) ? 1 : 2);
    if (mode == 2) {
        for (int i = threadIdx.x; i < B_ * N_; i += blockDim.x)
            g_mask[i] = raw[i] ? 1 : 0;
    } else {
        for (int i = threadIdx.x; i < B_ * N_; i += blockDim.x)
            g_mask[i] = w[i] ? 1 : 0;
    }
}

// ---------------------------------------------------------------------------
// TF32 GEMM: C[M,N] = A[M,K] @ B[K,N] (row-major fp32 in/out)
// 128x128 block, BK=32, 256 threads = 8 warps, warp tile 64x32.
// ---------------------------------------------------------------------------
#define AS_STR 36
#define BS_STR 136
__global__ __launch_bounds__(256) void gemm_tf32(
    const float* __restrict__ A, const float* __restrict__ Bm,
    float* __restrict__ C, int Mdim, int Ndim, int Kdim)
{
    __shared__ unsigned As[128 * AS_STR];
    __shared__ unsigned Bs[32 * BS_STR];

    const int tid  = threadIdx.x;
    const int warp = tid >> 5, lane = tid & 31;
    const int g = lane >> 2, t = lane & 3;
    const int wm = (warp >> 2) * 64;   // 0 or 64
    const int wn = (warp & 3) * 32;    // 0,32,64,96
    const int rowBase = blockIdx.y * 128;
    const int colBase = blockIdx.x * 128;

    float acc[4][4][4];
#pragma unroll
    for (int i = 0; i < 4; ++i)
#pragma unroll
        for (int j = 0; j < 4; ++j)
#pragma unroll
            for (int k = 0; k < 4; ++k) acc[i][j][k] = 0.f;

    for (int k0 = 0; k0 < Kdim; k0 += 32) {
        // A chunk: 128 x 32
#pragma unroll
        for (int i = 0; i < 4; ++i) {
            int f = tid + i * 256;
            int r = f >> 3, c = (f & 7) * 4;
            float4 v = *(const float4*)(A + (size_t)(rowBase + r) * Kdim + k0 + c);
            As[r * AS_STR + c + 0] = f2tf(v.x);
            As[r * AS_STR + c + 1] = f2tf(v.y);
            As[r * AS_STR + c + 2] = f2tf(v.z);
            As[r * AS_STR + c + 3] = f2tf(v.w);
        }
        // B chunk: 32 x 128
#pragma unroll
        for (int i = 0; i < 4; ++i) {
            int f = tid + i * 256;
            int r = f >> 5, c = (f & 31) * 4;
            float4 v = *(const float4*)(Bm + (size_t)(k0 + r) * Ndim + colBase + c);
            Bs[r * BS_STR + c + 0] = f2tf(v.x);
            Bs[r * BS_STR + c + 1] = f2tf(v.y);
            Bs[r * BS_STR + c + 2] = f2tf(v.z);
            Bs[r * BS_STR + c + 3] = f2tf(v.w);
        }
        __syncthreads();

#pragma unroll
        for (int kk = 0; kk < 4; ++kk) {
            const int kb = kk * 8;
            unsigned a[4][4], b[4][2];
#pragma unroll
            for (int mt = 0; mt < 4; ++mt) {
                int mr = wm + mt * 16;
                a[mt][0] = As[(mr + g) * AS_STR + kb + t];
                a[mt][1] = As[(mr + g + 8) * AS_STR + kb + t];
                a[mt][2] = As[(mr + g) * AS_STR + kb + t + 4];
                a[mt][3] = As[(mr + g + 8) * AS_STR + kb + t + 4];
            }
#pragma unroll
            for (int nt = 0; nt < 4; ++nt) {
                int nc = wn + nt * 8 + g;
                b[nt][0] = Bs[(kb + t) * BS_STR + nc];
                b[nt][1] = Bs[(kb + t + 4) * BS_STR + nc];
            }
#pragma unroll
            for (int mt = 0; mt < 4; ++mt)
#pragma unroll
                for (int nt = 0; nt < 4; ++nt)
                    mma8(acc[mt][nt], a[mt][0], a[mt][1], a[mt][2], a[mt][3],
                         b[nt][0], b[nt][1]);
        }
        __syncthreads();
    }

    // epilogue
#pragma unroll
    for (int mt = 0; mt < 4; ++mt) {
        int r0 = rowBase + wm + mt * 16 + g;
#pragma unroll
        for (int nt = 0; nt < 4; ++nt) {
            int c0 = colBase + wn + nt * 8 + 2 * t;
            *(float2*)(C + (size_t)r0 * Ndim + c0) =
                make_float2(acc[mt][nt][0], acc[mt][nt][1]);
            *(float2*)(C + (size_t)(r0 + 8) * Ndim + c0) =
                make_float2(acc[mt][nt][2], acc[mt][nt][3]);
        }
    }
}

// ---------------------------------------------------------------------------
// TF32 flash attention. Block = 64 query rows of one (b,h). 4 warps x 16 rows.
// Grid: (M/64, NH, B). Dynamic smem.
// ---------------------------------------------------------------------------
#define QS_STR 68
#define KS_STR 68
#define VS_STR 72
#define PS_STR 68
#define QS_OFF 0
#define KS_OFF (64 * QS_STR)                  // 4352
#define VS_OFF (KS_OFF + 64 * KS_STR)         // 8704
#define PS_OFF (VS_OFF + 64 * VS_STR)         // 13312
#define MB_OFF (PS_OFF + 64 * PS_STR)         // 17664
#define SMEM_WORDS (MB_OFF + 64)              // 17728 u32 = 70912 B

#define M_INIT (-1.0e4f)
#define MASK_BIAS (-1.0e9f)

__global__ __launch_bounds__(128) void attn_tc(
    const float* __restrict__ Q, const float* __restrict__ K,
    const float* __restrict__ V, float* __restrict__ Cout)
{
    extern __shared__ unsigned smemu[];
    unsigned* Qs = smemu + QS_OFF;
    unsigned* Ks = smemu + KS_OFF;
    unsigned* Vs = smemu + VS_OFF;
    unsigned* Ps = smemu + PS_OFF;
    float* mbias = (float*)(smemu + MB_OFF);

    const int mtile = blockIdx.x, h = blockIdx.y, b = blockIdx.z;
    const int tid = threadIdx.x;
    const int warp = tid >> 5, lane = tid & 31;
    const int g = lane >> 2, t = lane & 3;
    const int mb = warp * 16;                 // row base within 64

    // Load Q tile (scale and log2e folded in)
    {
        const int r = tid >> 1, ch = (tid & 1) * 32;
        const float SC = 0.125f * 1.44269504f;
        const float4* qrow = (const float4*)(Q + ((size_t)(b * M_ + mtile * 64 + r)) * D_ + h * DH_ + ch);
#pragma unroll
        for (int i = 0; i < 8; ++i) {
            float4 v = qrow[i];
            Qs[r * QS_STR + ch + 4 * i + 0] = f2tf(v.x * SC);
            Qs[r * QS_STR + ch + 4 * i + 1] = f2tf(v.y * SC);
            Qs[r * QS_STR + ch + 4 * i + 2] = f2tf(v.z * SC);
            Qs[r * QS_STR + ch + 4 * i + 3] = f2tf(v.w * SC);
        }
    }

    float m0 = M_INIT, m1 = M_INIT, l0 = 0.f, l1 = 0.f;
    float o[8][4];
#pragma unroll
    for (int i = 0; i < 8; ++i)
#pragma unroll
        for (int j = 0; j < 4; ++j) o[i][j] = 0.f;

    for (int kt = 0; kt < N_ / 64; ++kt) {
        __syncthreads();  // previous tile's Ks/Vs fully consumed
        {
            const int r = tid >> 1, ch = (tid & 1) * 32;
            const float4* krow = (const float4*)(K + ((size_t)(b * N_ + kt * 64 + r)) * D_ + h * DH_ + ch);
            const float4* vrow = (const float4*)(V + ((size_t)(b * N_ + kt * 64 + r)) * D_ + h * DH_ + ch);
#pragma unroll
            for (int i = 0; i < 8; ++i) {
                float4 kv = krow[i];
                Ks[r * KS_STR + ch + 4 * i + 0] = f2tf(kv.x);
                Ks[r * KS_STR + ch + 4 * i + 1] = f2tf(kv.y);
                Ks[r * KS_STR + ch + 4 * i + 2] = f2tf(kv.z);
                Ks[r * KS_STR + ch + 4 * i + 3] = f2tf(kv.w);
            }
#pragma unroll
            for (int i = 0; i < 8; ++i) {
                float4 vv = vrow[i];
                Vs[r * VS_STR + ch + 4 * i + 0] = f2tf(vv.x);
                Vs[r * VS_STR + ch + 4 * i + 1] = f2tf(vv.y);
                Vs[r * VS_STR + ch + 4 * i + 2] = f2tf(vv.z);
                Vs[r * VS_STR + ch + 4 * i + 3] = f2tf(vv.w);
            }
            if (tid < 64)
                mbias[tid] = g_mask[b * N_ + kt * 64 + tid] ? MASK_BIAS : 0.f;
        }
        __syncthreads();

        // S = Q K^T  (per warp: m16 x n64, k=64)
        float s[8][4];
#pragma unroll
        for (int i = 0; i < 8; ++i)
#pragma unroll
            for (int j = 0; j < 4; ++j) s[i][j] = 0.f;

#pragma unroll
        for (int kk = 0; kk < 8; ++kk) {
            const int kb = kk * 8;
            unsigned a0 = Qs[(mb + g) * QS_STR + kb + t];
            unsigned a1 = Qs[(mb + g + 8) * QS_STR + kb + t];
            unsigned a2 = Qs[(mb + g) * QS_STR + kb + t + 4];
            unsigned a3 = Qs[(mb + g + 8) * QS_STR + kb + t + 4];
#pragma unroll
            for (int nt = 0; nt < 8; ++nt) {
                unsigned b0 = Ks[(nt * 8 + g) * KS_STR + kb + t];
                unsigned b1 = Ks[(nt * 8 + g) * KS_STR + kb + t + 4];
                mma8(s[nt], a0, a1, a2, a3, b0, b1);
            }
        }

        // online softmax (base-2 domain)
        float mx0 = -3.0e38f, mx1 = -3.0e38f;
#pragma unroll
        for (int nt = 0; nt < 8; ++nt) {
            float b0 = mbias[nt * 8 + 2 * t];
            float b1 = mbias[nt * 8 + 2 * t + 1];
            s[nt][0] += b0; s[nt][1] += b1;
            s[nt][2] += b0; s[nt][3] += b1;
            mx0 = fmaxf(mx0, fmaxf(s[nt][0], s[nt][1]));
            mx1 = fmaxf(mx1, fmaxf(s[nt][2], s[nt][3]));
        }
        mx0 = fmaxf(mx0, __shfl_xor_sync(0xFFFFFFFFu, mx0, 1));
        mx0 = fmaxf(mx0, __shfl_xor_sync(0xFFFFFFFFu, mx0, 2));
        mx1 = fmaxf(mx1, __shfl_xor_sync(0xFFFFFFFFu, mx1, 1));
        mx1 = fmaxf(mx1, __shfl_xor_sync(0xFFFFFFFFu, mx1, 2));
        float nm0 = fmaxf(m0, mx0), nm1 = fmaxf(m1, mx1);
        float cr0 = ex2(m0 - nm0), cr1 = ex2(m1 - nm1);
        m0 = nm0; m1 = nm1;

        float rs0 = 0.f, rs1 = 0.f;
#pragma unroll
        for (int nt = 0; nt < 8; ++nt) {
            s[nt][0] = ex2(s[nt][0] - nm0);
            s[nt][1] = ex2(s[nt][1] - nm0);
            s[nt][2] = ex2(s[nt][2] - nm1);
            s[nt][3] = ex2(s[nt][3] - nm1);
            rs0 += s[nt][0] + s[nt][1];
            rs1 += s[nt][2] + s[nt][3];
        }
        l0 = l0 * cr0 + rs0;
        l1 = l1 * cr1 + rs1;

        // rescale O, write P (tf32) to warp-private smem rows
#pragma unroll
        for (int nt = 0; nt < 8; ++nt) {
            o[nt][0] *= cr0; o[nt][1] *= cr0;
            o[nt][2] *= cr1; o[nt][3] *= cr1;
            Ps[(mb + g) * PS_STR + nt * 8 + 2 * t]         = f2tf(s[nt][0]);
            Ps[(mb + g) * PS_STR + nt * 8 + 2 * t + 1]     = f2tf(s[nt][1]);
            Ps[(mb + g + 8) * PS_STR + nt * 8 + 2 * t]     = f2tf(s[nt][2]);
            Ps[(mb + g + 8) * PS_STR + nt * 8 + 2 * t + 1] = f2tf(s[nt][3]);
        }
        __syncwarp();

        // O += P V  (per warp: m16 x n64(dh), k=64(keys))
#pragma unroll
        for (int kk = 0; kk < 8; ++kk) {
            const int kb = kk * 8;
            unsigned a0 = Ps[(mb + g) * PS_STR + kb + t];
            unsigned a1 = Ps[(mb + g + 8) * PS_STR + kb + t];
            unsigned a2 = Ps[(mb + g) * PS_STR + kb + t + 4];
            unsigned a3 = Ps[(mb + g + 8) * PS_STR + kb + t + 4];
#pragma unroll
            for (int nt = 0; nt < 8; ++nt) {
                unsigned b0 = Vs[(kb + t) * VS_STR + nt * 8 + g];
                unsigned b1 = Vs[(kb + t + 4) * VS_STR + nt * 8 + g];
                mma8(o[nt], a0, a1, a2, a3, b0, b1);
            }
        }
        __syncwarp();  // Ps reads done before next tile rewrites
    }

    // finalize
    l0 += __shfl_xor_sync(0xFFFFFFFFu, l0, 1);
    l0 += __shfl_xor_sync(0xFFFFFFFFu, l0, 2);
    l1 += __shfl_xor_sync(0xFFFFFFFFu, l1, 1);
    l1 += __shfl_xor_sync(0xFFFFFFFFu, l1, 2);
    float inv0 = 1.f / l0, inv1 = 1.f / l1;

    const int gr0 = mtile * 64 + mb + g;
    const int gr1 = gr0 + 8;
#pragma unroll
    for (int nt = 0; nt < 8; ++nt) {
        int col = h * DH_ + nt * 8 + 2 * t;
        *(float2*)(Cout + ((size_t)(b * M_ + gr0)) * D_ + col) =
            make_float2(o[nt][0] * inv0, o[nt][1] * inv0);
        *(float2*)(Cout + ((size_t)(b * M_ + gr1)) * D_ + col) =
            make_float2(o[nt][2] * inv1, o[nt][3] * inv1);
    }
}

// ---------------------------------------------------------------------------
// Launch. Inputs: query, key_value, key_padding_mask, W_Q, W_K, W_V, W_O
// ---------------------------------------------------------------------------
extern "C" void kernel_launch(void* const* d_in, const int* in_sizes, int n_in,
                              void* d_out, int out_size)
{
    const float* query = (const float*)d_in[0];
    const float* keyv  = (const float*)d_in[1];
    const unsigned char* mask_raw = (const unsigned char*)d_in[2];
    const float* W_Q = (const float*)d_in[3];
    const float* W_K = (const float*)d_in[4];
    const float* W_V = (const float*)d_in[5];
    const float* W_O = (const float*)d_in[6];
    float* out = (float*)d_out;

    float *gQ, *gK, *gV, *gC;
    cudaGetSymbolAddress((void**)&gQ, g_Q);
    cudaGetSymbolAddress((void**)&gK, g_K);
    cudaGetSymbolAddress((void**)&gV, g_V);
    cudaGetSymbolAddress((void**)&gC, g_C);

    cudaFuncSetAttribute(attn_tc, cudaFuncAttributeMaxDynamicSharedMemorySize,
                         SMEM_WORDS * 4);

    mask_expand_kernel<<<1, 1024>>>(mask_raw);

    dim3 gproj(D_ / 128, (B_ * M_) / 128);
    gemm_tf32<<<gproj, 256>>>(query, W_Q, gQ, B_ * M_, D_, D_);
    gemm_tf32<<<gproj, 256>>>(keyv,  W_K, gK, B_ * N_, D_, D_);
    gemm_tf32<<<gproj, 256>>>(keyv,  W_V, gV, B_ * N_, D_, D_);

    dim3 gattn(M_ / 64, NH_, B_);
    attn_tc<<<gattn, 128, SMEM_WORDS * 4>>>(gQ, gK, gV, gC);

    dim3 gout(D_ / 128, (B_ * M_) / 128);
    gemm_tf32<<<gout, 256>>>(gC, W_O, out, B_ * M_, D_, D_);
}